// round 4
// baseline (speedup 1.0000x reference)
#include <cuda_runtime.h>
#include <cuda_bf16.h>
#include <stdint.h>

#define NMAX 100000
#define EMAX 1600000
#define FT   128          // in_ft == out_ft == 128

// ---------------- device scratch (allocation-free) ----------------
__device__ float g_fts[NMAX * FT];     // linear transform result [N,128]
__device__ int   g_deg[NMAX];          // per-dst degree
__device__ int   g_off[NMAX + 1];      // CSR offsets
__device__ int   g_pos[NMAX];          // scatter cursors
__device__ int2  g_edge[EMAX];         // dst-grouped {src, val_bits}
__device__ int   g_part[512];          // scan partials

// ---------------- packed f32x2 helpers ----------------
#define PACK_F32X2(out, lo, hi) \
    asm("mov.b64 %0, {%1, %2};" : "=l"(out) : "f"(lo), "f"(hi))
#define UNPACK_F32X2(lo, hi, in) \
    asm("mov.b64 {%0, %1}, %2;" : "=f"(lo), "=f"(hi) : "l"(in))
#define FMA_F32X2(acc, a, b) \
    asm("fma.rn.f32x2 %0, %1, %2, %0;" : "+l"(acc) : "l"(a), "l"(b))

// ---------------- 1) GEMM: fts = seq @ W^T  (fp32, mov-free FFMA2) --------
// block = 256 threads (8 warps).
// smem: Wt[k][o] 128x128 f32 (64KB)  +  Ind[warp][r][k] duplicated-b u64 (64KB).
// Warp computes 8 rows x 128 outs; lane owns 4 contiguous outs as 2 f32x2 accs.
// Inner loop: w-pairs read as ulonglong2 views of Wt (pairs contiguous -> no
// packing); b-pairs read pre-duplicated from Ind (broadcast LDS.128).
__global__ void __launch_bounds__(256, 1)
gemm_kernel(const float* __restrict__ seq,
            const float* __restrict__ W,
            int n)
{
    extern __shared__ float sm[];
    float* Wt = sm;                                            // 128*128 f32
    unsigned long long* Ind = (unsigned long long*)(sm + FT * FT); // 8*8*128 u64

    const int tid  = threadIdx.x;
    const int warp = tid >> 5;
    const int lane = tid & 31;

    // load W transposed into smem: Wt[k*128+o] = W[o*128+k]
    for (int idx = tid; idx < FT * FT; idx += 256) {
        int o = idx >> 7;
        int k = idx & 127;
        Wt[k * FT + o] = W[idx];
    }

    // load 8 rows of seq for this warp, duplicated: Ind[r][k] = (b,b)
    const int rowBase = blockIdx.x * 64 + warp * 8;
    unsigned long long* myIn = Ind + warp * (8 * FT);
    for (int i = lane; i < 256; i += 32) {
        int r  = i >> 5;          // 0..7
        int c4 = i & 31;          // float4 index within row
        float4 v = make_float4(0.f, 0.f, 0.f, 0.f);
        int row = rowBase + r;
        if (row < n)
            v = ((const float4*)(seq + (size_t)row * FT))[c4];
        unsigned long long d;
        PACK_F32X2(d, v.x, v.x); myIn[r * FT + 4 * c4 + 0] = d;
        PACK_F32X2(d, v.y, v.y); myIn[r * FT + 4 * c4 + 1] = d;
        PACK_F32X2(d, v.z, v.z); myIn[r * FT + 4 * c4 + 2] = d;
        PACK_F32X2(d, v.w, v.w); myIn[r * FT + 4 * c4 + 3] = d;
    }
    __syncthreads();

    // accumulators: per row, (o0,o1) pair and (o2,o3) pair
    unsigned long long accA[8], accB[8];
#pragma unroll
    for (int r = 0; r < 8; r++) { accA[r] = 0ull; accB[r] = 0ull; }

    const ulonglong2* Wt2  = (const ulonglong2*)Wt;     // [k][lane] pair-pairs
    const ulonglong2* myB  = (const ulonglong2*)myIn;   // [r][k/2] dup pairs

    for (int k4 = 0; k4 < FT / 4; k4++) {
        // w pairs for 4 consecutive k: each LDS.128 = ((wx,wy),(wz,ww))
        ulonglong2 w0 = Wt2[(4 * k4 + 0) * 32 + lane];
        ulonglong2 w1 = Wt2[(4 * k4 + 1) * 32 + lane];
        ulonglong2 w2 = Wt2[(4 * k4 + 2) * 32 + lane];
        ulonglong2 w3 = Wt2[(4 * k4 + 3) * 32 + lane];
#pragma unroll
        for (int r = 0; r < 8; r++) {
            // bA = ((b0,b0),(b1,b1)), bB = ((b2,b2),(b3,b3)) : broadcast
            ulonglong2 bA = myB[r * 64 + 2 * k4];
            ulonglong2 bB = myB[r * 64 + 2 * k4 + 1];
            FMA_F32X2(accA[r], bA.x, w0.x); FMA_F32X2(accB[r], bA.x, w0.y);
            FMA_F32X2(accA[r], bA.y, w1.x); FMA_F32X2(accB[r], bA.y, w1.y);
            FMA_F32X2(accA[r], bB.x, w2.x); FMA_F32X2(accB[r], bB.x, w2.y);
            FMA_F32X2(accA[r], bB.y, w3.x); FMA_F32X2(accB[r], bB.y, w3.y);
        }
    }

#pragma unroll
    for (int r = 0; r < 8; r++) {
        int row = rowBase + r;
        if (row < n) {
            float4 o;
            UNPACK_F32X2(o.x, o.y, accA[r]);
            UNPACK_F32X2(o.z, o.w, accB[r]);
            ((float4*)(g_fts + (size_t)row * FT))[lane] = o;
        }
    }
}

// ---------------- 2) histogram of dst ----------------
__global__ void hist_kernel(const int* __restrict__ dst, int e)
{
    int i = blockIdx.x * blockDim.x + threadIdx.x;
    if (i < e) atomicAdd(&g_deg[dst[i]], 1);
}

// ---------------- 3) scan: per-chunk partial sums ----------------
__global__ void scan_partials(int n)
{
    __shared__ int s[256];
    int i = blockIdx.x * 256 + threadIdx.x;
    int v = (i < n) ? g_deg[i] : 0;
    s[threadIdx.x] = v;
    __syncthreads();
    for (int d = 128; d > 0; d >>= 1) {
        if (threadIdx.x < d) s[threadIdx.x] += s[threadIdx.x + d];
        __syncthreads();
    }
    if (threadIdx.x == 0) g_part[blockIdx.x] = s[0];
}

// ---------------- 4) scan: write offsets (computes own chunk prefix) -------
__global__ void scan_write(int n, int nchunks)
{
    __shared__ int s[256];
    __shared__ int base_sh;
    const int t = threadIdx.x;
    const int b = blockIdx.x;

    {
        int acc = 0;
        for (int c = t; c < b; c += 256) acc += g_part[c];
        s[t] = acc;
        __syncthreads();
        for (int d = 128; d > 0; d >>= 1) {
            if (t < d) s[t] += s[t + d];
            __syncthreads();
        }
        if (t == 0) base_sh = s[0];
        __syncthreads();
    }
    const int base = base_sh;
    __syncthreads();

    int i = b * 256 + t;
    int v = (i < n) ? g_deg[i] : 0;
    s[t] = v;
    __syncthreads();
    for (int d = 1; d < 256; d <<= 1) {
        int tmp = (t >= d) ? s[t - d] : 0;
        __syncthreads();
        s[t] += tmp;
        __syncthreads();
    }
    int incl = s[t];
    int excl = incl - v;
    if (i < n) {
        int off = base + excl;
        g_off[i] = off;
        g_pos[i] = off;
    }
    if (b == nchunks - 1 && t == 255)
        g_off[n] = base + incl;
}

// ---------------- 5) scatter edges into dst-grouped {src,val} pairs --------
__global__ void scatter_kernel(const int*   __restrict__ dst,
                               const int*   __restrict__ src,
                               const float* __restrict__ val,
                               int e)
{
    int i = blockIdx.x * blockDim.x + threadIdx.x;
    if (i < e) {
        int idx = atomicAdd(&g_pos[dst[i]], 1);
        g_edge[idx] = make_int2(src[i], __float_as_int(val[i]));
    }
}

// ---------------- 6) SpMM gather: warp per dst node, uniform edge loads ----
// All lanes read the SAME g_edge element (1 sector, L1-resident line reused
// 16x) — no shfl. Edge meta and fts rows batched 8-wide for MLP.
__global__ void __launch_bounds__(256, 8)
spmm_kernel(const float* __restrict__ bias,
            const float* __restrict__ prelu_a,
            float* __restrict__ out,
            int n)
{
    const int warp = (blockIdx.x * blockDim.x + threadIdx.x) >> 5;
    const int lane = threadIdx.x & 31;
    if (warp >= n) return;

    const int off0 = g_off[warp];
    const int off1 = g_off[warp + 1];

    float4 acc = make_float4(0.f, 0.f, 0.f, 0.f);
    const float4* fts4 = (const float4*)g_fts;

    int e = off0;
    for (; e + 8 <= off1; e += 8) {
        int2 p[8];
#pragma unroll
        for (int j = 0; j < 8; j++) p[j] = g_edge[e + j];   // uniform loads
        float4 f[8];
#pragma unroll
        for (int j = 0; j < 8; j++) f[j] = fts4[p[j].x * 32 + lane];
#pragma unroll
        for (int j = 0; j < 8; j++) {
            float v = __int_as_float(p[j].y);
            acc.x += v * f[j].x;
            acc.y += v * f[j].y;
            acc.z += v * f[j].z;
            acc.w += v * f[j].w;
        }
    }
    for (; e < off1; e++) {
        int2 p = g_edge[e];
        float v = __int_as_float(p.y);
        float4 f = fts4[p.x * 32 + lane];
        acc.x += v * f.x;
        acc.y += v * f.y;
        acc.z += v * f.z;
        acc.w += v * f.w;
    }

    float4 b4 = ((const float4*)bias)[lane];
    float  a  = prelu_a[0];
    float4 o;
    o.x = acc.x + b4.x; o.y = acc.y + b4.y;
    o.z = acc.z + b4.z; o.w = acc.w + b4.w;
    o.x = (o.x >= 0.f) ? o.x : a * o.x;
    o.y = (o.y >= 0.f) ? o.y : a * o.y;
    o.z = (o.z >= 0.f) ? o.z : a * o.z;
    o.w = (o.w >= 0.f) ? o.w : a * o.w;
    ((float4*)(out + (size_t)warp * FT))[lane] = o;
}

// ---------------- side-stream handles (created at program load) ------------
struct AuxStreams {
    cudaStream_t s2;
    cudaEvent_t  evFork, evJoin;
    AuxStreams() {
        cudaStreamCreateWithFlags(&s2, cudaStreamNonBlocking);
        cudaEventCreateWithFlags(&evFork, cudaEventDisableTiming);
        cudaEventCreateWithFlags(&evJoin, cudaEventDisableTiming);
    }
};
static AuxStreams g_aux;

// ---------------- launcher ----------------
extern "C" void kernel_launch(void* const* d_in, const int* in_sizes, int n_in,
                              void* d_out, int out_size)
{
    const float* seq      = (const float*)d_in[0];
    const float* W        = (const float*)d_in[1];
    const float* bias     = (const float*)d_in[2];
    const float* prelu_a  = (const float*)d_in[3];
    const float* edge_val = (const float*)d_in[4];
    const int*   edge_src = (const int*)  d_in[5];
    const int*   edge_dst = (const int*)  d_in[6];

    const int n = in_sizes[0] / FT;     // 100000
    const int e = in_sizes[4];          // 1600000

    // fork: branch B (CSR build) runs on side stream s2
    cudaEventRecord(g_aux.evFork, 0);
    cudaStreamWaitEvent(g_aux.s2, g_aux.evFork, 0);

    // ----- branch B: CSR build on s2 -----
    void* deg_ptr = nullptr;
    cudaGetSymbolAddress(&deg_ptr, g_deg);
    cudaMemsetAsync(deg_ptr, 0, (size_t)n * sizeof(int), g_aux.s2);
    hist_kernel<<<(e + 255) / 256, 256, 0, g_aux.s2>>>(edge_dst, e);
    const int nchunks = (n + 255) / 256;
    scan_partials<<<nchunks, 256, 0, g_aux.s2>>>(n);
    scan_write<<<nchunks, 256, 0, g_aux.s2>>>(n, nchunks);
    scatter_kernel<<<(e + 255) / 256, 256, 0, g_aux.s2>>>(edge_dst, edge_src, edge_val, e);
    cudaEventRecord(g_aux.evJoin, g_aux.s2);

    // ----- branch A: GEMM on default stream -----
    const int smem_bytes = (FT * FT) * sizeof(float)                 // Wt 64KB
                         + (8 * 8 * FT) * sizeof(unsigned long long);// Ind 64KB
    cudaFuncSetAttribute(gemm_kernel, cudaFuncAttributeMaxDynamicSharedMemorySize,
                         smem_bytes);
    gemm_kernel<<<(n + 63) / 64, 256, smem_bytes>>>(seq, W, n);

    // join, then SpMM (needs both branches)
    cudaStreamWaitEvent(0, g_aux.evJoin, 0);
    const int warps_per_block = 8;
    spmm_kernel<<<(n + warps_per_block - 1) / warps_per_block, warps_per_block * 32>>>(
        bias, prelu_a, (float*)d_out, n);
}

// round 6
// speedup vs baseline: 1.1744x; 1.1744x over previous
#include <cuda_runtime.h>
#include <cuda_bf16.h>
#include <stdint.h>

#define NMAX 100000
#define EMAX 1600000
#define FT   128          // in_ft == out_ft == 128

// ---------------- device scratch (allocation-free) ----------------
__device__ float g_fts[NMAX * FT];     // linear transform result [N,128]
__device__ int   g_deg[NMAX];          // per-dst degree (zero-init; re-zeroed by scatter)
__device__ int   g_off[NMAX + 1];      // CSR offsets
__device__ int   g_pos[NMAX];          // scatter cursors
__device__ int2  g_edge[EMAX];         // dst-grouped {src, val_bits}
__device__ int   g_part[512];          // scan partials

// ---------------- packed f32x2 helpers ----------------
#define PACK_F32X2(out, lo, hi) \
    asm("mov.b64 %0, {%1, %2};" : "=l"(out) : "f"(lo), "f"(hi))
#define UNPACK_F32X2(lo, hi, in) \
    asm("mov.b64 {%0, %1}, %2;" : "=f"(lo), "=f"(hi) : "l"(in))
#define FMA_F32X2(acc, a, b) \
    asm("fma.rn.f32x2 %0, %1, %2, %0;" : "+l"(acc) : "l"(a), "l"(b))

// ---------------- 1) GEMM: fts = seq @ W^T  (fp32, FFMA2) ------------------
// block = 256 threads (8 warps). smem: Wt[128][128] (64KB) + In[8][8][128] (32KB)
// = 96KB -> 2 blocks/SM. Warp computes 8 rows x 128 outs; lane owns 4 outs as
// 2 f32x2 accumulators. W-pairs are read directly as ulonglong2 views of Wt
// (adjacent floats = one f32x2 operand, no packing); b values are broadcast
// LDS.128 + 4 dup-packs per (r,k4).
__global__ void gemm_kernel(const float* __restrict__ seq,
                            const float* __restrict__ W,
                            int n)
{
    extern __shared__ float sm[];
    float* Wt = sm;               // [k][o] : 128*128
    float* In = sm + FT * FT;     // [warp][r][k] : 8*8*128

    const int tid  = threadIdx.x;
    const int warp = tid >> 5;
    const int lane = tid & 31;

    // load W transposed into smem: Wt[k*128+o] = W[o*128+k]
    for (int idx = tid; idx < FT * FT; idx += 256) {
        int o = idx >> 7;
        int k = idx & 127;
        Wt[k * FT + o] = W[idx];
    }

    // load 8 rows of seq for this warp (256 float4 per warp)
    const int rowBase = blockIdx.x * 64 + warp * 8;
    float* myIn = In + warp * (8 * FT);
    for (int i = lane; i < 256; i += 32) {
        int r  = i >> 5;          // 0..7
        int c4 = i & 31;          // float4 index within row
        float4 v = make_float4(0.f, 0.f, 0.f, 0.f);
        int row = rowBase + r;
        if (row < n)
            v = ((const float4*)(seq + (size_t)row * FT))[c4];
        ((float4*)myIn)[i] = v;
    }
    __syncthreads();

    // accumulators: per row, (o0,o1) pair and (o2,o3) pair
    unsigned long long accA[8], accB[8];
#pragma unroll
    for (int r = 0; r < 8; r++) { accA[r] = 0ull; accB[r] = 0ull; }

    const ulonglong2* Wt2   = (const ulonglong2*)Wt;   // [k][lane]: ((w0,w1),(w2,w3))
    const float4*     myIn4 = (const float4*)myIn;

    for (int k4 = 0; k4 < FT / 4; k4++) {
        ulonglong2 w0 = Wt2[(4 * k4 + 0) * 32 + lane];
        ulonglong2 w1 = Wt2[(4 * k4 + 1) * 32 + lane];
        ulonglong2 w2 = Wt2[(4 * k4 + 2) * 32 + lane];
        ulonglong2 w3 = Wt2[(4 * k4 + 3) * 32 + lane];
#pragma unroll
        for (int r = 0; r < 8; r++) {
            float4 b = myIn4[r * 32 + k4];
            unsigned long long bb;
            PACK_F32X2(bb, b.x, b.x);
            FMA_F32X2(accA[r], bb, w0.x); FMA_F32X2(accB[r], bb, w0.y);
            PACK_F32X2(bb, b.y, b.y);
            FMA_F32X2(accA[r], bb, w1.x); FMA_F32X2(accB[r], bb, w1.y);
            PACK_F32X2(bb, b.z, b.z);
            FMA_F32X2(accA[r], bb, w2.x); FMA_F32X2(accB[r], bb, w2.y);
            PACK_F32X2(bb, b.w, b.w);
            FMA_F32X2(accA[r], bb, w3.x); FMA_F32X2(accB[r], bb, w3.y);
        }
    }

#pragma unroll
    for (int r = 0; r < 8; r++) {
        int row = rowBase + r;
        if (row < n) {
            float4 o;
            UNPACK_F32X2(o.x, o.y, accA[r]);
            UNPACK_F32X2(o.z, o.w, accB[r]);
            ((float4*)(g_fts + (size_t)row * FT))[lane] = o;
        }
    }
}

// ---------------- 2) histogram of dst ----------------
// g_deg arrives zeroed: static zero-init on first call, re-zeroed by
// scatter_kernel at the end of every previous launch sequence.
__global__ void hist_kernel(const int* __restrict__ dst, int e)
{
    int i = blockIdx.x * blockDim.x + threadIdx.x;
    if (i < e) atomicAdd(&g_deg[dst[i]], 1);
}

// ---------------- 3) scan: per-chunk partial sums ----------------
__global__ void scan_partials(int n)
{
    __shared__ int s[256];
    int i = blockIdx.x * 256 + threadIdx.x;
    int v = (i < n) ? g_deg[i] : 0;
    s[threadIdx.x] = v;
    __syncthreads();
    for (int d = 128; d > 0; d >>= 1) {
        if (threadIdx.x < d) s[threadIdx.x] += s[threadIdx.x + d];
        __syncthreads();
    }
    if (threadIdx.x == 0) g_part[blockIdx.x] = s[0];
}

// ---------------- 4) scan: write offsets (computes own chunk prefix) -------
__global__ void scan_write(int n, int nchunks)
{
    __shared__ int s[256];
    __shared__ int base_sh;
    const int t = threadIdx.x;
    const int b = blockIdx.x;

    {
        int acc = 0;
        for (int c = t; c < b; c += 256) acc += g_part[c];
        s[t] = acc;
        __syncthreads();
        for (int d = 128; d > 0; d >>= 1) {
            if (t < d) s[t] += s[t + d];
            __syncthreads();
        }
        if (t == 0) base_sh = s[0];
        __syncthreads();
    }
    const int base = base_sh;
    __syncthreads();

    int i = b * 256 + t;
    int v = (i < n) ? g_deg[i] : 0;
    s[t] = v;
    __syncthreads();
    for (int d = 1; d < 256; d <<= 1) {
        int tmp = (t >= d) ? s[t - d] : 0;
        __syncthreads();
        s[t] += tmp;
        __syncthreads();
    }
    int incl = s[t];
    int excl = incl - v;
    if (i < n) {
        int off = base + excl;
        g_off[i] = off;
        g_pos[i] = off;
    }
    if (b == nchunks - 1 && t == 255)
        g_off[n] = base + incl;
}

// ---------------- 5) scatter edges + re-zero g_deg for the next replay -----
__global__ void scatter_kernel(const int*   __restrict__ dst,
                               const int*   __restrict__ src,
                               const float* __restrict__ val,
                               int e, int n)
{
    int i = blockIdx.x * blockDim.x + threadIdx.x;
    if (i < e) {
        int idx = atomicAdd(&g_pos[dst[i]], 1);
        g_edge[idx] = make_int2(src[i], __float_as_int(val[i]));
    }
    // g_deg is dead after scan_write; reset it here so the next launch
    // sequence (graph replay) starts from zero without a separate memset.
    if (i < n) g_deg[i] = 0;
}

// ---------------- 6) SpMM gather: warp per dst node, no float atomics ------
__global__ void spmm_kernel(const float* __restrict__ bias,
                            const float* __restrict__ prelu_a,
                            float* __restrict__ out,
                            int n)
{
    const int warp = (blockIdx.x * blockDim.x + threadIdx.x) >> 5;
    const int lane = threadIdx.x & 31;
    if (warp >= n) return;

    const int off0 = g_off[warp];
    const int off1 = g_off[warp + 1];

    float4 acc = make_float4(0.f, 0.f, 0.f, 0.f);
    const float4* fts4 = (const float4*)g_fts;

    for (int base = off0; base < off1; base += 32) {
        int e = base + lane;
        int   s = 0;
        float v = 0.f;
        if (e < off1) {
            int2 p = g_edge[e];      // coalesced 8B read
            s = p.x;
            v = __int_as_float(p.y);
        }
        int cnt = min(32, off1 - base);
#pragma unroll 8
        for (int j = 0; j < cnt; j++) {
            int   sj = __shfl_sync(0xffffffffu, s, j);
            float vj = __shfl_sync(0xffffffffu, v, j);
            float4 f = fts4[(size_t)sj * 32 + lane];
            acc.x += vj * f.x;
            acc.y += vj * f.y;
            acc.z += vj * f.z;
            acc.w += vj * f.w;
        }
    }

    float4 b4 = ((const float4*)bias)[lane];
    float  a  = prelu_a[0];
    float4 o;
    o.x = acc.x + b4.x; o.y = acc.y + b4.y;
    o.z = acc.z + b4.z; o.w = acc.w + b4.w;
    o.x = (o.x >= 0.f) ? o.x : a * o.x;
    o.y = (o.y >= 0.f) ? o.y : a * o.y;
    o.z = (o.z >= 0.f) ? o.z : a * o.z;
    o.w = (o.w >= 0.f) ? o.w : a * o.w;
    ((float4*)(out + (size_t)warp * FT))[lane] = o;
}

// ---------------- side-stream handles (created at program load) ------------
struct AuxStreams {
    cudaStream_t s2;
    cudaEvent_t  evFork, evJoin;
    AuxStreams() {
        cudaStreamCreateWithFlags(&s2, cudaStreamNonBlocking);
        cudaEventCreateWithFlags(&evFork, cudaEventDisableTiming);
        cudaEventCreateWithFlags(&evJoin, cudaEventDisableTiming);
    }
};
static AuxStreams g_aux;

// ---------------- launcher ----------------
extern "C" void kernel_launch(void* const* d_in, const int* in_sizes, int n_in,
                              void* d_out, int out_size)
{
    const float* seq      = (const float*)d_in[0];
    const float* W        = (const float*)d_in[1];
    const float* bias     = (const float*)d_in[2];
    const float* prelu_a  = (const float*)d_in[3];
    const float* edge_val = (const float*)d_in[4];
    const int*   edge_src = (const int*)  d_in[5];
    const int*   edge_dst = (const int*)  d_in[6];

    const int n = in_sizes[0] / FT;     // 100000
    const int e = in_sizes[4];          // 1600000

    // fork: branch B (CSR build) runs on side stream s2
    cudaEventRecord(g_aux.evFork, 0);
    cudaStreamWaitEvent(g_aux.s2, g_aux.evFork, 0);

    // ----- branch B: CSR build on s2 (launches #1..#4) -----
    hist_kernel<<<(e + 255) / 256, 256, 0, g_aux.s2>>>(edge_dst, e);
    const int nchunks = (n + 255) / 256;
    scan_partials<<<nchunks, 256, 0, g_aux.s2>>>(n);
    scan_write<<<nchunks, 256, 0, g_aux.s2>>>(n, nchunks);
    scatter_kernel<<<(e + 255) / 256, 256, 0, g_aux.s2>>>(edge_dst, edge_src, edge_val, e, n);
    cudaEventRecord(g_aux.evJoin, g_aux.s2);

    // ----- branch A: GEMM on default stream (launch #5) -----
    const int smem_bytes = (FT * FT + 8 * 8 * FT) * sizeof(float);  // 96KB
    cudaFuncSetAttribute(gemm_kernel, cudaFuncAttributeMaxDynamicSharedMemorySize,
                         smem_bytes);
    gemm_kernel<<<(n + 63) / 64, 256, smem_bytes>>>(seq, W, n);

    // join, then SpMM (launch #6 — profiled by ncu -s 5 -c 1)
    cudaStreamWaitEvent(0, g_aux.evJoin, 0);
    const int warps_per_block = 8;
    spmm_kernel<<<(n + warps_per_block - 1) / warps_per_block, warps_per_block * 32>>>(
        bias, prelu_a, (float*)d_out, n);
}

// round 8
// speedup vs baseline: 1.3099x; 1.1153x over previous
#include <cuda_runtime.h>
#include <cuda_bf16.h>
#include <mma.h>
#include <stdint.h>

using namespace nvcuda;

#define NMAX 100000
#define NPAD 100032        // NMAX rounded up to 64 (whole-tile stores at tail)
#define EMAX 1600000
#define FT   128           // in_ft == out_ft == 128

// ---------------- device scratch (allocation-free) ----------------
__device__ float         g_fts[NPAD * FT]; // linear transform result [N,128] (padded)
__device__ __nv_bfloat16 g_Whi[FT * FT];   // W hi bf16
__device__ __nv_bfloat16 g_Wlo[FT * FT];   // W residual bf16
__device__ int   g_deg[NMAX];              // per-dst degree (zero-init; re-zeroed by scatter)
__device__ int   g_off[NMAX + 1];          // CSR offsets
__device__ int   g_pos[NMAX];              // scatter cursors
__device__ int2  g_edge[EMAX];             // dst-grouped {src, val_bits}
__device__ int   g_part[512];              // scan partials

// ---------------- 0) split W into bf16 hi/lo ----------------
__global__ void w_split_kernel(const float* __restrict__ W)
{
    int i = blockIdx.x * blockDim.x + threadIdx.x;
    if (i < FT * FT) {
        float w = W[i];
        __nv_bfloat16 hi = __float2bfloat16(w);
        float lo = w - __bfloat162float(hi);
        g_Whi[i] = hi;
        g_Wlo[i] = __float2bfloat16(lo);
    }
}

// ---------------- 1) GEMM: fts = seq @ W^T via WMMA bf16-split -------------
// block = 256 threads (8 warps), 64 rows x 128 cols per block.
// smem: A tile hi/lo bf16 [64][128] each = 32KB.
// Warp w: rows [(w&3)*16, +16), cols [(w>>2)*64, +64) = 4 acc tiles of 16x16.
// D = Ah*Bh + Ah*Bl + Al*Bh with fp32 accumulation (AlBl dropped, ~2^-18 rel).
// B fragments (W^T) load directly from global g_Whi/g_Wlo: W is [o][k] row-major,
// so B(k,o) col_major with ld=128 reads ptr[o*128+k] = W[o][k] = W^T[k][o].  OK
__global__ void __launch_bounds__(256)
gemm_wmma_kernel(const float* __restrict__ seq, int n)
{
    __shared__ __nv_bfloat16 Ahi[64 * FT];
    __shared__ __nv_bfloat16 Alo[64 * FT];

    const int tid = threadIdx.x;
    const int wid = tid >> 5;
    const int rowBase = blockIdx.x * 64;

    // convert 64 seq rows to bf16 hi/lo in smem (2048 float4, 8 per thread)
    for (int i = tid; i < 64 * 32; i += 256) {
        int row = i >> 5;
        int c4  = i & 31;
        float4 v = make_float4(0.f, 0.f, 0.f, 0.f);
        int grow = rowBase + row;
        if (grow < n)
            v = ((const float4*)(seq + (size_t)grow * FT))[c4];
        __nv_bfloat16 h0 = __float2bfloat16(v.x);
        __nv_bfloat16 h1 = __float2bfloat16(v.y);
        __nv_bfloat16 h2 = __float2bfloat16(v.z);
        __nv_bfloat16 h3 = __float2bfloat16(v.w);
        __nv_bfloat162* dh = (__nv_bfloat162*)(Ahi + row * FT + c4 * 4);
        dh[0] = __nv_bfloat162(h0, h1);
        dh[1] = __nv_bfloat162(h2, h3);
        __nv_bfloat162* dl = (__nv_bfloat162*)(Alo + row * FT + c4 * 4);
        dl[0] = __nv_bfloat162(__float2bfloat16(v.x - __bfloat162float(h0)),
                               __float2bfloat16(v.y - __bfloat162float(h1)));
        dl[1] = __nv_bfloat162(__float2bfloat16(v.z - __bfloat162float(h2)),
                               __float2bfloat16(v.w - __bfloat162float(h3)));
    }
    __syncthreads();

    const int mrow    = (wid & 3) * 16;
    const int colBase = (wid >> 2) * 64;

    wmma::fragment<wmma::accumulator, 16, 16, 16, float> acc[4];
#pragma unroll
    for (int ct = 0; ct < 4; ct++) wmma::fill_fragment(acc[ct], 0.0f);

#pragma unroll
    for (int kt = 0; kt < 8; kt++) {
        const int k = kt * 16;
        wmma::fragment<wmma::matrix_a, 16, 16, 16, __nv_bfloat16, wmma::row_major> ah, al;
        wmma::load_matrix_sync(ah, Ahi + mrow * FT + k, FT);
        wmma::load_matrix_sync(al, Alo + mrow * FT + k, FT);
#pragma unroll
        for (int ct = 0; ct < 4; ct++) {
            const int col = colBase + ct * 16;
            wmma::fragment<wmma::matrix_b, 16, 16, 16, __nv_bfloat16, wmma::col_major> bh, bl;
            wmma::load_matrix_sync(bh, g_Whi + (size_t)col * FT + k, FT);
            wmma::load_matrix_sync(bl, g_Wlo + (size_t)col * FT + k, FT);
            wmma::mma_sync(acc[ct], ah, bh, acc[ct]);
            wmma::mma_sync(acc[ct], ah, bl, acc[ct]);
            wmma::mma_sync(acc[ct], al, bh, acc[ct]);
        }
    }

#pragma unroll
    for (int ct = 0; ct < 4; ct++) {
        float* dst = g_fts + (size_t)(rowBase + mrow) * FT + colBase + ct * 16;
        wmma::store_matrix_sync(dst, acc[ct], FT, wmma::mem_row_major);
    }
}

// ---------------- 2) histogram of dst ----------------
// g_deg arrives zeroed: static zero-init on first call, re-zeroed by
// scatter_kernel at the end of every previous launch sequence.
__global__ void hist_kernel(const int* __restrict__ dst, int e)
{
    int i = blockIdx.x * blockDim.x + threadIdx.x;
    if (i < e) atomicAdd(&g_deg[dst[i]], 1);
}

// ---------------- 3) scan: per-chunk partial sums ----------------
__global__ void scan_partials(int n)
{
    __shared__ int s[256];
    int i = blockIdx.x * 256 + threadIdx.x;
    int v = (i < n) ? g_deg[i] : 0;
    s[threadIdx.x] = v;
    __syncthreads();
    for (int d = 128; d > 0; d >>= 1) {
        if (threadIdx.x < d) s[threadIdx.x] += s[threadIdx.x + d];
        __syncthreads();
    }
    if (threadIdx.x == 0) g_part[blockIdx.x] = s[0];
}

// ---------------- 4) scan: write offsets (computes own chunk prefix) -------
__global__ void scan_write(int n, int nchunks)
{
    __shared__ int s[256];
    __shared__ int base_sh;
    const int t = threadIdx.x;
    const int b = blockIdx.x;

    {
        int acc = 0;
        for (int c = t; c < b; c += 256) acc += g_part[c];
        s[t] = acc;
        __syncthreads();
        for (int d = 128; d > 0; d >>= 1) {
            if (t < d) s[t] += s[t + d];
            __syncthreads();
        }
        if (t == 0) base_sh = s[0];
        __syncthreads();
    }
    const int base = base_sh;
    __syncthreads();

    int i = b * 256 + t;
    int v = (i < n) ? g_deg[i] : 0;
    s[t] = v;
    __syncthreads();
    for (int d = 1; d < 256; d <<= 1) {
        int tmp = (t >= d) ? s[t - d] : 0;
        __syncthreads();
        s[t] += tmp;
        __syncthreads();
    }
    int incl = s[t];
    int excl = incl - v;
    if (i < n) {
        int off = base + excl;
        g_off[i] = off;
        g_pos[i] = off;
    }
    if (b == nchunks - 1 && t == 255)
        g_off[n] = base + incl;
}

// ---------------- 5) scatter edges + re-zero g_deg for the next replay -----
__global__ void scatter_kernel(const int*   __restrict__ dst,
                               const int*   __restrict__ src,
                               const float* __restrict__ val,
                               int e, int n)
{
    int i = blockIdx.x * blockDim.x + threadIdx.x;
    if (i < e) {
        int idx = atomicAdd(&g_pos[dst[i]], 1);
        g_edge[idx] = make_int2(src[i], __float_as_int(val[i]));
    }
    // g_deg is dead after scan_write; reset it here so the next replay
    // starts from zero without a separate memset launch.
    if (i < n) g_deg[i] = 0;
}

// ---------------- 6) SpMM gather: warp per dst node, no float atomics ------
__global__ void spmm_kernel(const float* __restrict__ bias,
                            const float* __restrict__ prelu_a,
                            float* __restrict__ out,
                            int n)
{
    const int warp = (blockIdx.x * blockDim.x + threadIdx.x) >> 5;
    const int lane = threadIdx.x & 31;
    if (warp >= n) return;

    const int off0 = g_off[warp];
    const int off1 = g_off[warp + 1];

    float4 acc = make_float4(0.f, 0.f, 0.f, 0.f);
    const float4* fts4 = (const float4*)g_fts;

    for (int base = off0; base < off1; base += 32) {
        int e = base + lane;
        int   s = 0;
        float v = 0.f;
        if (e < off1) {
            int2 p = g_edge[e];      // coalesced 8B read
            s = p.x;
            v = __int_as_float(p.y);
        }
        int cnt = min(32, off1 - base);
#pragma unroll 8
        for (int j = 0; j < cnt; j++) {
            int   sj = __shfl_sync(0xffffffffu, s, j);
            float vj = __shfl_sync(0xffffffffu, v, j);
            float4 f = fts4[(size_t)sj * 32 + lane];
            acc.x += vj * f.x;
            acc.y += vj * f.y;
            acc.z += vj * f.z;
            acc.w += vj * f.w;
        }
    }

    float4 b4 = ((const float4*)bias)[lane];
    float  a  = prelu_a[0];
    float4 o;
    o.x = acc.x + b4.x; o.y = acc.y + b4.y;
    o.z = acc.z + b4.z; o.w = acc.w + b4.w;
    o.x = (o.x >= 0.f) ? o.x : a * o.x;
    o.y = (o.y >= 0.f) ? o.y : a * o.y;
    o.z = (o.z >= 0.f) ? o.z : a * o.z;
    o.w = (o.w >= 0.f) ? o.w : a * o.w;
    ((float4*)(out + (size_t)warp * FT))[lane] = o;
}

// ---------------- side-stream handles (created at program load) ------------
struct AuxStreams {
    cudaStream_t s2;
    cudaEvent_t  evFork, evJoin;
    AuxStreams() {
        cudaStreamCreateWithFlags(&s2, cudaStreamNonBlocking);
        cudaEventCreateWithFlags(&evFork, cudaEventDisableTiming);
        cudaEventCreateWithFlags(&evJoin, cudaEventDisableTiming);
    }
};
static AuxStreams g_aux;

// ---------------- launcher ----------------
extern "C" void kernel_launch(void* const* d_in, const int* in_sizes, int n_in,
                              void* d_out, int out_size)
{
    const float* seq      = (const float*)d_in[0];
    const float* W        = (const float*)d_in[1];
    const float* bias     = (const float*)d_in[2];
    const float* prelu_a  = (const float*)d_in[3];
    const float* edge_val = (const float*)d_in[4];
    const int*   edge_src = (const int*)  d_in[5];
    const int*   edge_dst = (const int*)  d_in[6];

    const int n = in_sizes[0] / FT;     // 100000
    const int e = in_sizes[4];          // 1600000

    // fork: branch B (CSR build) runs on side stream s2
    cudaEventRecord(g_aux.evFork, 0);
    cudaStreamWaitEvent(g_aux.s2, g_aux.evFork, 0);

    // ----- branch B: CSR build on s2 -----
    hist_kernel<<<(e + 255) / 256, 256, 0, g_aux.s2>>>(edge_dst, e);
    const int nchunks = (n + 255) / 256;
    scan_partials<<<nchunks, 256, 0, g_aux.s2>>>(n);
    scan_write<<<nchunks, 256, 0, g_aux.s2>>>(n, nchunks);
    scatter_kernel<<<(e + 255) / 256, 256, 0, g_aux.s2>>>(edge_dst, edge_src, edge_val, e, n);
    cudaEventRecord(g_aux.evJoin, g_aux.s2);

    // ----- branch A: WMMA bf16-split GEMM on default stream -----
    w_split_kernel<<<(FT * FT + 255) / 256, 256>>>(W);
    gemm_wmma_kernel<<<(n + 63) / 64, 256>>>(seq, n);

    // join, then SpMM (needs both branches)
    cudaStreamWaitEvent(0, g_aux.evJoin, 0);
    const int warps_per_block = 8;
    spmm_kernel<<<(n + warps_per_block - 1) / warps_per_block, warps_per_block * 32>>>(
        bias, prelu_a, (float*)d_out, n);
}